// round 9
// baseline (speedup 1.0000x reference)
#include <cuda_runtime.h>
#include <cuda_bf16.h>
#include <cstdint>

#define NN 8192
#define IN_F 128
#define OUT_F 64
#define ALPHA 0.2f

#define TI 128                 // CTA row tile
#define BK 128                 // j per B stage
#define SPLITS 8
#define JSPAN (NN / SPLITS)    // 1024
#define NTI (NN / TI)          // 64

#define BSTRIDE 272            // bytes per n-row in B stage (128*2 + 16 pad) -> conflict-free
#define BHALF 17408            // 64 * 272

// dynamic smem layout for attn
#define OFF_BS   0                         // 2*BHALF = 34816
#define OFF_S2   (2 * BHALF)               // 4096
#define OFF_ADJ  (2 * BHALF + 4096)        // 3 * 10240 = 30720
#define ADJSTRIDE 80                       // bytes per adj row (64 data + 16 pad)
#define ADJBUF   (TI * ADJSTRIDE)          // 10240
#define SMEM_TOTAL (OFF_ADJ + 3 * ADJBUF)  // 69632

// Scratch
__device__ float g_s1[NN];
__device__ float g_s2[NN];
__device__ __nv_bfloat16 g_WhT_hi[OUT_F * NN];   // transposed Wh, bf16 hi
__device__ __nv_bfloat16 g_WhT_lo[OUT_F * NN];   // bf16 residual
__device__ float g_accP[SPLITS][NN][OUT_F];
__device__ float g_lP[SPLITS][NN];

// pack two fp32 -> {low16=bf16(x0), high16=bf16(x1)} by truncation
__device__ __forceinline__ uint32_t pack_bf16(float x0, float x1) {
    return __byte_perm(__float_as_uint(x0), __float_as_uint(x1), 0x7632);
}
__device__ __forceinline__ float bf16_trunc_f(float x) {
    return __uint_as_float(__float_as_uint(x) & 0xFFFF0000u);
}

__device__ __forceinline__ void mma16816(float* d,
                                         uint32_t a0, uint32_t a1, uint32_t a2, uint32_t a3,
                                         uint32_t b0, uint32_t b1) {
    asm volatile(
        "mma.sync.aligned.m16n8k16.row.col.f32.bf16.bf16.f32 "
        "{%0,%1,%2,%3}, {%4,%5,%6,%7}, {%8,%9}, {%0,%1,%2,%3};"
        : "+f"(d[0]), "+f"(d[1]), "+f"(d[2]), "+f"(d[3])
        : "r"(a0), "r"(a1), "r"(a2), "r"(a3), "r"(b0), "r"(b1));
}

__device__ __forceinline__ uint32_t smem_u32(const void* p) {
    uint32_t a;
    asm("{ .reg .u64 t; cvta.to.shared.u64 t, %1; cvt.u32.u64 %0, t; }" : "=r"(a) : "l"(p));
    return a;
}
__device__ __forceinline__ void cp16(uint32_t dst, const void* src) {
    asm volatile("cp.async.cg.shared.global [%0], [%1], 16;" :: "r"(dst), "l"(src));
}
#define CP_COMMIT() asm volatile("cp.async.commit_group;" ::: "memory")
#define CP_WAIT1()  asm volatile("cp.async.wait_group 1;" ::: "memory")
#define CP_WAIT0()  asm volatile("cp.async.wait_group 0;" ::: "memory")

// ---------------------------------------------------------------------------
// Kernel 1: Wh = h@W; s1 = Wh@a1; s2 = Wh@a2; WhT hi/lo bf16 split.
// (round-6 version, measured 24.8us)
// ---------------------------------------------------------------------------
__global__ __launch_bounds__(256) void wh_kernel(const float* __restrict__ h,
                                                 const float* __restrict__ W,
                                                 const float* __restrict__ a) {
    __shared__ float W_s[IN_F * OUT_F];
    __shared__ float h_s[4][IN_F];
    __shared__ float a_s[2 * OUT_F];
    __shared__ float red1[8], red2[8];
    __shared__ float tr[OUT_F][17];

    const int t = threadIdx.x;
    const int blockRow = blockIdx.x * 16;

    for (int i = t; i < IN_F * OUT_F; i += 256) W_s[i] = W[i];
    if (t < 2 * OUT_F) a_s[t] = a[t];

    const int g = t >> 6;
    const int c = t & 63;

    for (int rg = 0; rg < 4; ++rg) {
        const int rowBase = blockRow + rg * 4;
        __syncthreads();
        for (int i = t; i < 4 * IN_F; i += 256)
            h_s[i >> 7][i & 127] = h[(size_t)(rowBase + (i >> 7)) * IN_F + (i & 127)];
        __syncthreads();

        float acc = 0.f;
#pragma unroll 8
        for (int k = 0; k < IN_F; ++k)
            acc += h_s[g][k] * W_s[k * OUT_F + c];

        tr[c][rg * 4 + g] = acc;

        float v1 = acc * a_s[c];
        float v2 = acc * a_s[OUT_F + c];
#pragma unroll
        for (int off = 16; off > 0; off >>= 1) {
            v1 += __shfl_down_sync(0xffffffffu, v1, off);
            v2 += __shfl_down_sync(0xffffffffu, v2, off);
        }
        if ((t & 31) == 0) { red1[t >> 5] = v1; red2[t >> 5] = v2; }
        __syncthreads();
        if (t < 4) {
            g_s1[rowBase + t] = red1[2 * t] + red1[2 * t + 1];
            g_s2[rowBase + t] = red2[2 * t] + red2[2 * t + 1];
        }
    }
    __syncthreads();

    {
        const int cc = t >> 2;
        const int q = t & 3;
        float v[4], hi[4], lo[4];
#pragma unroll
        for (int i = 0; i < 4; ++i) {
            v[i] = tr[cc][q * 4 + i];
            hi[i] = bf16_trunc_f(v[i]);
            lo[i] = v[i] - hi[i];
        }
        size_t o = (size_t)cc * NN + blockRow + q * 4;
        *(uint2*)&g_WhT_hi[o] = make_uint2(pack_bf16(hi[0], hi[1]), pack_bf16(hi[2], hi[3]));
        *(uint2*)&g_WhT_lo[o] = make_uint2(pack_bf16(lo[0], lo[1]), pack_bf16(lo[2], lo[3]));
    }
}

// ---------------------------------------------------------------------------
// Kernel 2: mma.sync bf16 attention (round-6 body) + cp.async 3-buffer adj
// staging (register-free latency hiding). grid=(64, 8), 8 warps.
// ---------------------------------------------------------------------------
__global__ void __launch_bounds__(256) attn_kernel(const int* __restrict__ adj) {
    extern __shared__ __align__(16) unsigned char smem[];
    unsigned char* Bs = smem + OFF_BS;
    float* s2_s = (float*)(smem + OFF_S2);
    const uint32_t adjSmem = smem_u32(smem) + OFF_ADJ;

    const int t = threadIdx.x;
    const int wid = t >> 5;
    const int lane = t & 31;
    const int qr = lane >> 2;      // 0..7
    const int qm = lane & 3;       // 0..3

    const int iBase = blockIdx.x * TI;
    const int split = blockIdx.y;
    const int jStart = split * JSPAN;

    const int r0 = wid * 16 + qr;
    const int r1 = r0 + 8;
    const float s1r0 = g_s1[iBase + r0];
    const float s1r1 = g_s1[iBase + r1];

    const int* __restrict__ adjBase = adj + (size_t)iBase * NN + jStart;

    // chunk-granular cp.async issue: all 256 threads, 2 x 16B each (128 rows x 64B)
    auto issue_chunk = [&](int gc) {
        const int buf = gc % 3;
        const uint32_t dbase = adjSmem + buf * ADJBUF;
        const int* sbase = adjBase + gc * 16;
        {
            int row = t >> 2, seg = t & 3;
            cp16(dbase + row * ADJSTRIDE + seg * 16, sbase + (size_t)row * NN + seg * 4);
        }
        {
            int s = t + 256;
            int row = s >> 2, seg = s & 3;
            cp16(dbase + row * ADJSTRIDE + seg * 16, sbase + (size_t)row * NN + seg * 4);
        }
        CP_COMMIT();
    };

    // s2 span -> smem
    {
        const float4* src = (const float4*)&g_s2[jStart];
        ((float4*)s2_s)[t] = src[t];
    }

    // prologue: 2 chunks in flight
    issue_chunk(0);
    issue_chunk(1);

    float d[8][4];
#pragma unroll
    for (int nt = 0; nt < 8; ++nt)
#pragma unroll
        for (int i = 0; i < 4; ++i) d[nt][i] = 0.f;
    float lsum0 = 0.f, lsum1 = 0.f;

    for (int stage = 0; stage < JSPAN / BK; ++stage) {
        const int jStage = jStart + stage * BK;

        __syncthreads();   // prior stage's MMA B-reads done before overwriting Bs

        // ---- load B stage: WhT hi/lo bf16, 64 n-rows x 128 k, padded stride
        for (int idx = t; idx < 2048; idx += 256) {
            int half = idx >> 10;          // 0 = hi, 1 = lo
            int rem = idx & 1023;
            int n = rem >> 4;              // 0..63
            int seg = rem & 15;            // 16B segment
            const __nv_bfloat16* gsrc = (half ? g_WhT_lo : g_WhT_hi) + (size_t)n * NN + jStage;
            uint4 v = ((const uint4*)gsrc)[seg];
            *(uint4*)(Bs + half * BHALF + n * BSTRIDE + seg * 16) = v;
        }

        // ---- 8 chunks of 16 j
#pragma unroll 2
        for (int c = 0; c < 8; ++c) {
            const int gc = stage * 8 + c;         // global chunk 0..63
            const int jc = stage * BK + c * 16 + 2 * qm;

            // pipeline: ensure chunk gc's copies landed; publish to all threads.
            if (gc < 63) { CP_WAIT1(); } else { CP_WAIT0(); }
            __syncthreads();   // adjS[gc] visible; (c==0) also publishes Bs stores
            if (gc + 2 < 64) issue_chunk(gc + 2);  // overwrites buffer of gc-1 (reads done)

            const unsigned char* ab =
                (const unsigned char*)smem + OFF_ADJ + (gc % 3) * ADJBUF;
            int2 A0 = *(const int2*)(ab + r0 * ADJSTRIDE + qm * 8);
            int2 A2 = *(const int2*)(ab + r0 * ADJSTRIDE + 32 + qm * 8);
            int2 A1 = *(const int2*)(ab + r1 * ADJSTRIDE + qm * 8);
            int2 A3 = *(const int2*)(ab + r1 * ADJSTRIDE + 32 + qm * 8);

            float2 s2a = *(const float2*)&s2_s[jc];
            float2 s2b = *(const float2*)&s2_s[jc + 8];

            float e, p00, p01, p02, p03, p10, p11, p12, p13;
            e = s1r0 + s2a.x; e = fmaxf(e, ALPHA * e); p00 = (A0.x > 0) ? __expf(e) : 0.f;
            e = s1r0 + s2a.y; e = fmaxf(e, ALPHA * e); p01 = (A0.y > 0) ? __expf(e) : 0.f;
            e = s1r0 + s2b.x; e = fmaxf(e, ALPHA * e); p02 = (A2.x > 0) ? __expf(e) : 0.f;
            e = s1r0 + s2b.y; e = fmaxf(e, ALPHA * e); p03 = (A2.y > 0) ? __expf(e) : 0.f;
            e = s1r1 + s2a.x; e = fmaxf(e, ALPHA * e); p10 = (A1.x > 0) ? __expf(e) : 0.f;
            e = s1r1 + s2a.y; e = fmaxf(e, ALPHA * e); p11 = (A1.y > 0) ? __expf(e) : 0.f;
            e = s1r1 + s2b.x; e = fmaxf(e, ALPHA * e); p12 = (A3.x > 0) ? __expf(e) : 0.f;
            e = s1r1 + s2b.y; e = fmaxf(e, ALPHA * e); p13 = (A3.y > 0) ? __expf(e) : 0.f;

            lsum0 += (p00 + p01) + (p02 + p03);
            lsum1 += (p10 + p11) + (p12 + p13);

            uint32_t a0h = pack_bf16(p00, p01), a2h = pack_bf16(p02, p03);
            uint32_t a1h = pack_bf16(p10, p11), a3h = pack_bf16(p12, p13);
            uint32_t a0l = pack_bf16(p00 - bf16_trunc_f(p00), p01 - bf16_trunc_f(p01));
            uint32_t a2l = pack_bf16(p02 - bf16_trunc_f(p02), p03 - bf16_trunc_f(p03));
            uint32_t a1l = pack_bf16(p10 - bf16_trunc_f(p10), p11 - bf16_trunc_f(p11));
            uint32_t a3l = pack_bf16(p12 - bf16_trunc_f(p12), p13 - bf16_trunc_f(p13));

            const int kOff = c * 32 + qm * 4;
#pragma unroll
            for (int nt = 0; nt < 8; ++nt) {
                const unsigned char* bp = Bs + (nt * 8 + qr) * BSTRIDE + kOff;
                uint32_t bh0 = *(const uint32_t*)bp;
                uint32_t bh1 = *(const uint32_t*)(bp + 16);
                uint32_t bl0 = *(const uint32_t*)(bp + BHALF);
                uint32_t bl1 = *(const uint32_t*)(bp + BHALF + 16);
                mma16816(d[nt], a0h, a1h, a2h, a3h, bh0, bh1);
                mma16816(d[nt], a0h, a1h, a2h, a3h, bl0, bl1);
                mma16816(d[nt], a0l, a1l, a2l, a3l, bh0, bh1);
            }
        }
    }

    // ---- row sums across the quad
    lsum0 += __shfl_xor_sync(0xffffffffu, lsum0, 1);
    lsum0 += __shfl_xor_sync(0xffffffffu, lsum0, 2);
    lsum1 += __shfl_xor_sync(0xffffffffu, lsum1, 1);
    lsum1 += __shfl_xor_sync(0xffffffffu, lsum1, 2);
    if (qm == 0) {
        g_lP[split][iBase + r0] = lsum0;
        g_lP[split][iBase + r1] = lsum1;
    }

    // ---- write partials
    {
        float* base0 = &g_accP[split][iBase + r0][0];
        float* base1 = &g_accP[split][iBase + r1][0];
#pragma unroll
        for (int nt = 0; nt < 8; ++nt) {
            int cb = nt * 8 + 2 * qm;
            *(float2*)&base0[cb] = make_float2(d[nt][0], d[nt][1]);
            *(float2*)&base1[cb] = make_float2(d[nt][2], d[nt][3]);
        }
    }
}

// ---------------------------------------------------------------------------
// Kernel 3: sum split partials -> normalize -> ELU.
// ---------------------------------------------------------------------------
__global__ __launch_bounds__(256) void combine_kernel(float* __restrict__ out) {
    __shared__ float linv_s[16];
    const int t = threadIdx.x;
    const int rowBase = blockIdx.x * 16;

    if (t < 16) {
        int row = rowBase + t;
        float L = 0.f;
#pragma unroll
        for (int s = 0; s < SPLITS; ++s) L += g_lP[s][row];
        linv_s[t] = 1.f / L;
    }
    __syncthreads();

    const int rr = t >> 4;
    const int c4 = t & 15;
    const int row = rowBase + rr;

    float4 acc = make_float4(0.f, 0.f, 0.f, 0.f);
#pragma unroll
    for (int s = 0; s < SPLITS; ++s) {
        float4 v = *(const float4*)&g_accP[s][row][c4 * 4];
        acc.x += v.x; acc.y += v.y; acc.z += v.z; acc.w += v.w;
    }
    float li = linv_s[rr];
    float x0 = acc.x * li, x1 = acc.y * li, x2 = acc.z * li, x3 = acc.w * li;
    x0 = (x0 > 0.f) ? x0 : expm1f(x0);
    x1 = (x1 > 0.f) ? x1 : expm1f(x1);
    x2 = (x2 > 0.f) ? x2 : expm1f(x2);
    x3 = (x3 > 0.f) ? x3 : expm1f(x3);
    *(float4*)&out[(size_t)row * OUT_F + c4 * 4] = make_float4(x0, x1, x2, x3);
}

// ---------------------------------------------------------------------------
extern "C" void kernel_launch(void* const* d_in, const int* in_sizes, int n_in,
                              void* d_out, int out_size) {
    const float* h   = (const float*)d_in[0];   // 8192 x 128
    const int*   adj = (const int*)d_in[1];     // 8192 x 8192
    const float* W   = (const float*)d_in[2];   // 128 x 64
    const float* a   = (const float*)d_in[3];   // 128 x 1
    float* out = (float*)d_out;                 // 8192 x 64

    // opt-in to >48KB dynamic smem (idempotent; no static guards)
    cudaFuncSetAttribute(attn_kernel, cudaFuncAttributeMaxDynamicSharedMemorySize,
                         SMEM_TOTAL);

    wh_kernel<<<NN / 16, 256>>>(h, W, a);
    attn_kernel<<<dim3(NTI, SPLITS), 256, SMEM_TOTAL>>>(adj);
    combine_kernel<<<NN / 16, 256>>>(out);
}

// round 10
// speedup vs baseline: 1.0155x; 1.0155x over previous
#include <cuda_runtime.h>
#include <cuda_bf16.h>
#include <cstdint>

#define NN 8192
#define IN_F 128
#define OUT_F 64
#define ALPHA 0.2f

#define TI 128                 // CTA row tile
#define BK 128                 // j per B stage
#define SPLITS 8
#define JSPAN (NN / SPLITS)    // 1024
#define NTI (NN / TI)          // 64

#define BSTRIDE 272            // bytes per n-row in B stage (128*2 + 16 pad) -> conflict-free
#define BHALF 17408            // 64 * 272

#define NWORDS (NN / 32)       // 256 bitmask words per row

// Scratch
__device__ float g_s1[NN];
__device__ float g_s2[NN];
__device__ __nv_bfloat16 g_WhT_hi[OUT_F * NN];   // transposed Wh, bf16 hi
__device__ __nv_bfloat16 g_WhT_lo[OUT_F * NN];   // bf16 residual
__device__ float g_accP[SPLITS][NN][OUT_F];
__device__ float g_lP[SPLITS][NN];
__device__ uint32_t g_adjBits[NN * NWORDS];      // 8 MB bit-packed adj

// pack two fp32 -> {low16=bf16(x0), high16=bf16(x1)} by truncation
__device__ __forceinline__ uint32_t pack_bf16(float x0, float x1) {
    return __byte_perm(__float_as_uint(x0), __float_as_uint(x1), 0x7632);
}
__device__ __forceinline__ float bf16_trunc_f(float x) {
    return __uint_as_float(__float_as_uint(x) & 0xFFFF0000u);
}

__device__ __forceinline__ void mma16816(float* d,
                                         uint32_t a0, uint32_t a1, uint32_t a2, uint32_t a3,
                                         uint32_t b0, uint32_t b1) {
    asm volatile(
        "mma.sync.aligned.m16n8k16.row.col.f32.bf16.bf16.f32 "
        "{%0,%1,%2,%3}, {%4,%5,%6,%7}, {%8,%9}, {%0,%1,%2,%3};"
        : "+f"(d[0]), "+f"(d[1]), "+f"(d[2]), "+f"(d[3])
        : "r"(a0), "r"(a1), "r"(a2), "r"(a3), "r"(b0), "r"(b1));
}

// ---------------------------------------------------------------------------
// Kernel 0: bit-pack adj (0/1 int32 -> 1 bit). Pure streaming, coalesced.
// Each warp packs 128 consecutive words (4096 ints).
// ---------------------------------------------------------------------------
__global__ __launch_bounds__(256) void pack_kernel(const int* __restrict__ adj) {
    const int lane = threadIdx.x & 31;
    const int warpId = (blockIdx.x * 256 + threadIdx.x) >> 5;   // 0..16383
    const int* __restrict__ base = adj + (size_t)warpId * 4096;
    uint32_t* __restrict__ dst = g_adjBits + warpId * 128;

#pragma unroll
    for (int g = 0; g < 4; ++g) {
        uint32_t myword = 0;
#pragma unroll
        for (int k = 0; k < 32; ++k) {
            int v = __ldg(base + (g * 32 + k) * 32 + lane);
            uint32_t b = __ballot_sync(0xffffffffu, v > 0);
            if (lane == k) myword = b;
        }
        dst[g * 32 + lane] = myword;   // coalesced 128B store per warp
    }
}

// ---------------------------------------------------------------------------
// Kernel 1: Wh = h@W; s1 = Wh@a1; s2 = Wh@a2; WhT hi/lo bf16 split.
// (round-6 version, measured 24.8us)
// ---------------------------------------------------------------------------
__global__ __launch_bounds__(256) void wh_kernel(const float* __restrict__ h,
                                                 const float* __restrict__ W,
                                                 const float* __restrict__ a) {
    __shared__ float W_s[IN_F * OUT_F];
    __shared__ float h_s[4][IN_F];
    __shared__ float a_s[2 * OUT_F];
    __shared__ float red1[8], red2[8];
    __shared__ float tr[OUT_F][17];

    const int t = threadIdx.x;
    const int blockRow = blockIdx.x * 16;

    for (int i = t; i < IN_F * OUT_F; i += 256) W_s[i] = W[i];
    if (t < 2 * OUT_F) a_s[t] = a[t];

    const int g = t >> 6;
    const int c = t & 63;

    for (int rg = 0; rg < 4; ++rg) {
        const int rowBase = blockRow + rg * 4;
        __syncthreads();
        for (int i = t; i < 4 * IN_F; i += 256)
            h_s[i >> 7][i & 127] = h[(size_t)(rowBase + (i >> 7)) * IN_F + (i & 127)];
        __syncthreads();

        float acc = 0.f;
#pragma unroll 8
        for (int k = 0; k < IN_F; ++k)
            acc += h_s[g][k] * W_s[k * OUT_F + c];

        tr[c][rg * 4 + g] = acc;

        float v1 = acc * a_s[c];
        float v2 = acc * a_s[OUT_F + c];
#pragma unroll
        for (int off = 16; off > 0; off >>= 1) {
            v1 += __shfl_down_sync(0xffffffffu, v1, off);
            v2 += __shfl_down_sync(0xffffffffu, v2, off);
        }
        if ((t & 31) == 0) { red1[t >> 5] = v1; red2[t >> 5] = v2; }
        __syncthreads();
        if (t < 4) {
            g_s1[rowBase + t] = red1[2 * t] + red1[2 * t + 1];
            g_s2[rowBase + t] = red2[2 * t] + red2[2 * t + 1];
        }
    }
    __syncthreads();

    {
        const int cc = t >> 2;
        const int q = t & 3;
        float v[4], hi[4], lo[4];
#pragma unroll
        for (int i = 0; i < 4; ++i) {
            v[i] = tr[cc][q * 4 + i];
            hi[i] = bf16_trunc_f(v[i]);
            lo[i] = v[i] - hi[i];
        }
        size_t o = (size_t)cc * NN + blockRow + q * 4;
        *(uint2*)&g_WhT_hi[o] = make_uint2(pack_bf16(hi[0], hi[1]), pack_bf16(hi[2], hi[3]));
        *(uint2*)&g_WhT_lo[o] = make_uint2(pack_bf16(lo[0], lo[1]), pack_bf16(lo[2], lo[3]));
    }
}

// ---------------------------------------------------------------------------
// Kernel 2: mma.sync bf16 attention (round-6 body), adj via bitmask:
// one uint4 (128 bits) per warp-row per stage, register-resident.
// grid=(64 i-tiles, 8 splits), 8 warps.
// ---------------------------------------------------------------------------
__global__ void __launch_bounds__(256) attn_kernel() {
    __shared__ __align__(16) unsigned char Bs[2 * BHALF];  // hi | lo, 64 rows x 272B
    __shared__ __align__(16) float s2_s[JSPAN];

    const int t = threadIdx.x;
    const int wid = t >> 5;
    const int lane = t & 31;
    const int qr = lane >> 2;      // 0..7
    const int qm = lane & 3;       // 0..3

    const int iBase = blockIdx.x * TI;
    const int split = blockIdx.y;
    const int jStart = split * JSPAN;

    const int r0 = wid * 16 + qr;      // local row for a0/a2
    const int r1 = r0 + 8;             // a1/a3
    const float s1r0 = g_s1[iBase + r0];
    const float s1r1 = g_s1[iBase + r1];
    const uint32_t* __restrict__ bitsRow0 = g_adjBits + (size_t)(iBase + r0) * NWORDS;
    const uint32_t* __restrict__ bitsRow1 = g_adjBits + (size_t)(iBase + r1) * NWORDS;

    // s2 span -> smem
    {
        const float4* src = (const float4*)&g_s2[jStart];
        ((float4*)s2_s)[t] = src[t];
    }

    float d[8][4];
#pragma unroll
    for (int nt = 0; nt < 8; ++nt)
#pragma unroll
        for (int i = 0; i < 4; ++i) d[nt][i] = 0.f;
    float lsum0 = 0.f, lsum1 = 0.f;

    for (int stage = 0; stage < JSPAN / BK; ++stage) {
        const int jStage = jStart + stage * BK;

        __syncthreads();   // prior MMAs done before overwriting Bs (also covers s2 on stage 0)

        // adj bits for this stage: 128 bits per row (one uint4), register-resident.
        // Issued before B staging so the staging loads hide their latency.
        const int wBase = jStage >> 5;      // multiple of 4 -> uint4 aligned
        uint4 bits0 = __ldg((const uint4*)(bitsRow0 + wBase));
        uint4 bits1 = __ldg((const uint4*)(bitsRow1 + wBase));

        // ---- load B stage: WhT hi/lo bf16, 64 n-rows x 128 k, padded stride
        for (int idx = t; idx < 2048; idx += 256) {
            int half = idx >> 10;          // 0 = hi, 1 = lo
            int rem = idx & 1023;
            int n = rem >> 4;              // 0..63
            int seg = rem & 15;            // 16B segment
            const __nv_bfloat16* gsrc = (half ? g_WhT_lo : g_WhT_hi) + (size_t)n * NN + jStage;
            uint4 v = ((const uint4*)gsrc)[seg];
            *(uint4*)(Bs + half * BHALF + n * BSTRIDE + seg * 16) = v;
        }
        __syncthreads();

        // ---- 8 chunks of 16 j, as 4 words x 2 halves (static register indexing)
        const uint32_t wd0a[4] = {bits0.x, bits0.y, bits0.z, bits0.w};
        const uint32_t wd1a[4] = {bits1.x, bits1.y, bits1.z, bits1.w};
#pragma unroll
        for (int w4 = 0; w4 < 4; ++w4) {
            const uint32_t wd0 = wd0a[w4];
            const uint32_t wd1 = wd1a[w4];
#pragma unroll
            for (int h2 = 0; h2 < 2; ++h2) {
                const int c = w4 * 2 + h2;
                const int jc = stage * BK + c * 16 + 2 * qm;   // local j (within span)
                const int sb = h2 * 16 + 2 * qm;               // bit base in word

                float2 s2a = *(const float2*)&s2_s[jc];
                float2 s2b = *(const float2*)&s2_s[jc + 8];

                float e, p00, p01, p02, p03, p10, p11, p12, p13;
                e = s1r0 + s2a.x; e = fmaxf(e, ALPHA * e); p00 = (wd0 >> sb       & 1u) ? __expf(e) : 0.f;
                e = s1r0 + s2a.y; e = fmaxf(e, ALPHA * e); p01 = (wd0 >> (sb + 1) & 1u) ? __expf(e) : 0.f;
                e = s1r0 + s2b.x; e = fmaxf(e, ALPHA * e); p02 = (wd0 >> (sb + 8) & 1u) ? __expf(e) : 0.f;
                e = s1r0 + s2b.y; e = fmaxf(e, ALPHA * e); p03 = (wd0 >> (sb + 9) & 1u) ? __expf(e) : 0.f;
                e = s1r1 + s2a.x; e = fmaxf(e, ALPHA * e); p10 = (wd1 >> sb       & 1u) ? __expf(e) : 0.f;
                e = s1r1 + s2a.y; e = fmaxf(e, ALPHA * e); p11 = (wd1 >> (sb + 1) & 1u) ? __expf(e) : 0.f;
                e = s1r1 + s2b.x; e = fmaxf(e, ALPHA * e); p12 = (wd1 >> (sb + 8) & 1u) ? __expf(e) : 0.f;
                e = s1r1 + s2b.y; e = fmaxf(e, ALPHA * e); p13 = (wd1 >> (sb + 9) & 1u) ? __expf(e) : 0.f;

                lsum0 += (p00 + p01) + (p02 + p03);
                lsum1 += (p10 + p11) + (p12 + p13);

                // hi/lo fragment packing (truncation split)
                uint32_t a0h = pack_bf16(p00, p01), a2h = pack_bf16(p02, p03);
                uint32_t a1h = pack_bf16(p10, p11), a3h = pack_bf16(p12, p13);
                uint32_t a0l = pack_bf16(p00 - bf16_trunc_f(p00), p01 - bf16_trunc_f(p01));
                uint32_t a2l = pack_bf16(p02 - bf16_trunc_f(p02), p03 - bf16_trunc_f(p03));
                uint32_t a1l = pack_bf16(p10 - bf16_trunc_f(p10), p11 - bf16_trunc_f(p11));
                uint32_t a3l = pack_bf16(p12 - bf16_trunc_f(p12), p13 - bf16_trunc_f(p13));

                // base byte offset within a B n-row for this chunk + lane k
                const int kOff = c * 32 + qm * 4;
#pragma unroll
                for (int nt = 0; nt < 8; ++nt) {
                    const unsigned char* bp = Bs + (nt * 8 + qr) * BSTRIDE + kOff;
                    uint32_t bh0 = *(const uint32_t*)bp;
                    uint32_t bh1 = *(const uint32_t*)(bp + 16);
                    uint32_t bl0 = *(const uint32_t*)(bp + BHALF);
                    uint32_t bl1 = *(const uint32_t*)(bp + BHALF + 16);
                    mma16816(d[nt], a0h, a1h, a2h, a3h, bh0, bh1);
                    mma16816(d[nt], a0h, a1h, a2h, a3h, bl0, bl1);
                    mma16816(d[nt], a0l, a1l, a2l, a3l, bh0, bh1);
                }
            }
        }
    }

    // ---- row sums: reduce across the 4 lanes of each quad-column group
    lsum0 += __shfl_xor_sync(0xffffffffu, lsum0, 1);
    lsum0 += __shfl_xor_sync(0xffffffffu, lsum0, 2);
    lsum1 += __shfl_xor_sync(0xffffffffu, lsum1, 1);
    lsum1 += __shfl_xor_sync(0xffffffffu, lsum1, 2);
    if (qm == 0) {
        g_lP[split][iBase + r0] = lsum0;
        g_lP[split][iBase + r1] = lsum1;
    }

    // ---- write partials: d[nt] = rows (r0, r1), cols nt*8 + 2*qm + {0,1}
    {
        float* base0 = &g_accP[split][iBase + r0][0];
        float* base1 = &g_accP[split][iBase + r1][0];
#pragma unroll
        for (int nt = 0; nt < 8; ++nt) {
            int cb = nt * 8 + 2 * qm;
            *(float2*)&base0[cb] = make_float2(d[nt][0], d[nt][1]);
            *(float2*)&base1[cb] = make_float2(d[nt][2], d[nt][3]);
        }
    }
}

// ---------------------------------------------------------------------------
// Kernel 3: sum split partials -> normalize -> ELU.
// ---------------------------------------------------------------------------
__global__ __launch_bounds__(256) void combine_kernel(float* __restrict__ out) {
    __shared__ float linv_s[16];
    const int t = threadIdx.x;
    const int rowBase = blockIdx.x * 16;

    if (t < 16) {
        int row = rowBase + t;
        float L = 0.f;
#pragma unroll
        for (int s = 0; s < SPLITS; ++s) L += g_lP[s][row];
        linv_s[t] = 1.f / L;
    }
    __syncthreads();

    const int rr = t >> 4;
    const int c4 = t & 15;
    const int row = rowBase + rr;

    float4 acc = make_float4(0.f, 0.f, 0.f, 0.f);
#pragma unroll
    for (int s = 0; s < SPLITS; ++s) {
        float4 v = *(const float4*)&g_accP[s][row][c4 * 4];
        acc.x += v.x; acc.y += v.y; acc.z += v.z; acc.w += v.w;
    }
    float li = linv_s[rr];
    float x0 = acc.x * li, x1 = acc.y * li, x2 = acc.z * li, x3 = acc.w * li;
    x0 = (x0 > 0.f) ? x0 : expm1f(x0);
    x1 = (x1 > 0.f) ? x1 : expm1f(x1);
    x2 = (x2 > 0.f) ? x2 : expm1f(x2);
    x3 = (x3 > 0.f) ? x3 : expm1f(x3);
    *(float4*)&out[(size_t)row * OUT_F + c4 * 4] = make_float4(x0, x1, x2, x3);
}

// ---------------------------------------------------------------------------
extern "C" void kernel_launch(void* const* d_in, const int* in_sizes, int n_in,
                              void* d_out, int out_size) {
    const float* h   = (const float*)d_in[0];   // 8192 x 128
    const int*   adj = (const int*)d_in[1];     // 8192 x 8192
    const float* W   = (const float*)d_in[2];   // 128 x 64
    const float* a   = (const float*)d_in[3];   // 128 x 1
    float* out = (float*)d_out;                 // 8192 x 64

    pack_kernel<<<2048, 256>>>(adj);            // adj -> 8MB bitmask
    wh_kernel<<<NN / 16, 256>>>(h, W, a);
    attn_kernel<<<dim3(NTI, SPLITS), 256>>>();
    combine_kernel<<<NN / 16, 256>>>(out);
}

// round 11
// speedup vs baseline: 1.4142x; 1.3925x over previous
#include <cuda_runtime.h>
#include <cuda_fp16.h>
#include <cstdint>

#define NN 8192
#define IN_F 128
#define OUT_F 64
#define ALPHA 0.2f

#define TI 128                 // CTA row tile
#define BK 128                 // j per B stage
#define SPLITS 8
#define JSPAN (NN / SPLITS)    // 1024
#define NTI (NN / TI)          // 64

#define BSTRIDE 272            // bytes per n-row in B stage (128*2 + 16 pad) -> conflict-free
#define BHALF 17408            // 64 * 272

// Scratch
__device__ float g_s1[NN];
__device__ float g_s2[NN];
__device__ __half g_WhT_hi[OUT_F * NN];   // transposed Wh, fp16 (RN)
__device__ __half g_WhT_lo[OUT_F * NN];   // fp16 residual
__device__ float g_accP[SPLITS][NN][OUT_F];
__device__ float g_lP[SPLITS][NN];

__device__ __forceinline__ uint32_t pack_half2(float x0, float x1) {
    __half2 h = __floats2half2_rn(x0, x1);
    return *(uint32_t*)&h;
}

__device__ __forceinline__ void mma16816f16(float* d,
                                            uint32_t a0, uint32_t a1, uint32_t a2, uint32_t a3,
                                            uint32_t b0, uint32_t b1) {
    asm volatile(
        "mma.sync.aligned.m16n8k16.row.col.f32.f16.f16.f32 "
        "{%0,%1,%2,%3}, {%4,%5,%6,%7}, {%8,%9}, {%0,%1,%2,%3};"
        : "+f"(d[0]), "+f"(d[1]), "+f"(d[2]), "+f"(d[3])
        : "r"(a0), "r"(a1), "r"(a2), "r"(a3), "r"(b0), "r"(b1));
}

// ---------------------------------------------------------------------------
// Kernel 1: Wh = h@W; s1 = Wh@a1; s2 = Wh@a2; WhT fp16 hi/lo split.
// (round-6 structure, measured 24.8us)
// ---------------------------------------------------------------------------
__global__ __launch_bounds__(256) void wh_kernel(const float* __restrict__ h,
                                                 const float* __restrict__ W,
                                                 const float* __restrict__ a) {
    __shared__ float W_s[IN_F * OUT_F];
    __shared__ float h_s[4][IN_F];
    __shared__ float a_s[2 * OUT_F];
    __shared__ float red1[8], red2[8];
    __shared__ float tr[OUT_F][17];

    const int t = threadIdx.x;
    const int blockRow = blockIdx.x * 16;

    for (int i = t; i < IN_F * OUT_F; i += 256) W_s[i] = W[i];
    if (t < 2 * OUT_F) a_s[t] = a[t];

    const int g = t >> 6;
    const int c = t & 63;

    for (int rg = 0; rg < 4; ++rg) {
        const int rowBase = blockRow + rg * 4;
        __syncthreads();
        for (int i = t; i < 4 * IN_F; i += 256)
            h_s[i >> 7][i & 127] = h[(size_t)(rowBase + (i >> 7)) * IN_F + (i & 127)];
        __syncthreads();

        float acc = 0.f;
#pragma unroll 8
        for (int k = 0; k < IN_F; ++k)
            acc += h_s[g][k] * W_s[k * OUT_F + c];

        tr[c][rg * 4 + g] = acc;

        float v1 = acc * a_s[c];
        float v2 = acc * a_s[OUT_F + c];
#pragma unroll
        for (int off = 16; off > 0; off >>= 1) {
            v1 += __shfl_down_sync(0xffffffffu, v1, off);
            v2 += __shfl_down_sync(0xffffffffu, v2, off);
        }
        if ((t & 31) == 0) { red1[t >> 5] = v1; red2[t >> 5] = v2; }
        __syncthreads();
        if (t < 4) {
            g_s1[rowBase + t] = red1[2 * t] + red1[2 * t + 1];
            g_s2[rowBase + t] = red2[2 * t] + red2[2 * t + 1];
        }
    }
    __syncthreads();

    // transposed fp16 hi/lo write-out: thread t -> col cc=t>>2, rows q*4..+3
    {
        const int cc = t >> 2;
        const int q = t & 3;
        float v[4], hi[4], lo[4];
#pragma unroll
        for (int i = 0; i < 4; ++i) {
            v[i] = tr[cc][q * 4 + i];
            hi[i] = __half2float(__float2half_rn(v[i]));
            lo[i] = v[i] - hi[i];
        }
        size_t o = (size_t)cc * NN + blockRow + q * 4;
        *(uint2*)&g_WhT_hi[o] = make_uint2(pack_half2(hi[0], hi[1]), pack_half2(hi[2], hi[3]));
        *(uint2*)&g_WhT_lo[o] = make_uint2(pack_half2(lo[0], lo[1]), pack_half2(lo[2], lo[3]));
    }
}

// ---------------------------------------------------------------------------
// Kernel 2: mma.sync fp16 attention (round-6 body, adj inline LDG).
// A = single fp16-RN fragment; B = fp16 hi + fp16 lo -> 2 MMAs per n-tile.
// grid=(64 i-tiles, 8 splits), 8 warps.
// ---------------------------------------------------------------------------
__global__ void __launch_bounds__(256) attn_kernel(const int* __restrict__ adj) {
    __shared__ __align__(16) unsigned char Bs[2 * BHALF];  // hi | lo, 64 rows x 272B
    __shared__ __align__(16) float s2_s[JSPAN];

    const int t = threadIdx.x;
    const int wid = t >> 5;
    const int lane = t & 31;
    const int qr = lane >> 2;      // 0..7
    const int qm = lane & 3;       // 0..3

    const int iBase = blockIdx.x * TI;
    const int split = blockIdx.y;
    const int jStart = split * JSPAN;

    const int r0 = wid * 16 + qr;      // local row for a0/a2
    const int r1 = r0 + 8;             // a1/a3
    const float s1r0 = g_s1[iBase + r0];
    const float s1r1 = g_s1[iBase + r1];
    const int* __restrict__ row0 = adj + (size_t)(iBase + r0) * NN;
    const int* __restrict__ row1 = adj + (size_t)(iBase + r1) * NN;

    // s2 span -> smem
    {
        const float4* src = (const float4*)&g_s2[jStart];
        ((float4*)s2_s)[t] = src[t];
    }

    float d[8][4];
#pragma unroll
    for (int nt = 0; nt < 8; ++nt)
#pragma unroll
        for (int i = 0; i < 4; ++i) d[nt][i] = 0.f;
    float lsum0 = 0.f, lsum1 = 0.f;

    for (int stage = 0; stage < JSPAN / BK; ++stage) {
        const int jStage = jStart + stage * BK;

        __syncthreads();   // prior MMAs done before overwriting Bs (also covers s2 on stage 0)

        // ---- load B stage: WhT hi/lo fp16, 64 n-rows x 128 k, padded stride
        for (int idx = t; idx < 2048; idx += 256) {
            int half = idx >> 10;          // 0 = hi, 1 = lo
            int rem = idx & 1023;
            int n = rem >> 4;              // 0..63
            int seg = rem & 15;            // 16B segment
            const __half* gsrc = (half ? g_WhT_lo : g_WhT_hi) + (size_t)n * NN + jStage;
            uint4 v = ((const uint4*)gsrc)[seg];
            *(uint4*)(Bs + half * BHALF + n * BSTRIDE + seg * 16) = v;
        }
        __syncthreads();

        // ---- 8 chunks of 16 j
#pragma unroll 2
        for (int c = 0; c < 8; ++c) {
            const int jc = stage * BK + c * 16 + 2 * qm;   // local j (within span)
            const int gj = jStage + c * 16 + 2 * qm;       // global j

            int2 A0 = __ldg((const int2*)(row0 + gj));
            int2 A2 = __ldg((const int2*)(row0 + gj + 8));
            int2 A1 = __ldg((const int2*)(row1 + gj));
            int2 A3 = __ldg((const int2*)(row1 + gj + 8));
            float2 s2a = *(const float2*)&s2_s[jc];
            float2 s2b = *(const float2*)&s2_s[jc + 8];

            float e, p00, p01, p02, p03, p10, p11, p12, p13;
            e = s1r0 + s2a.x; e = fmaxf(e, ALPHA * e); p00 = (A0.x > 0) ? __expf(e) : 0.f;
            e = s1r0 + s2a.y; e = fmaxf(e, ALPHA * e); p01 = (A0.y > 0) ? __expf(e) : 0.f;
            e = s1r0 + s2b.x; e = fmaxf(e, ALPHA * e); p02 = (A2.x > 0) ? __expf(e) : 0.f;
            e = s1r0 + s2b.y; e = fmaxf(e, ALPHA * e); p03 = (A2.y > 0) ? __expf(e) : 0.f;
            e = s1r1 + s2a.x; e = fmaxf(e, ALPHA * e); p10 = (A1.x > 0) ? __expf(e) : 0.f;
            e = s1r1 + s2a.y; e = fmaxf(e, ALPHA * e); p11 = (A1.y > 0) ? __expf(e) : 0.f;
            e = s1r1 + s2b.x; e = fmaxf(e, ALPHA * e); p12 = (A3.x > 0) ? __expf(e) : 0.f;
            e = s1r1 + s2b.y; e = fmaxf(e, ALPHA * e); p13 = (A3.y > 0) ? __expf(e) : 0.f;

            lsum0 += (p00 + p01) + (p02 + p03);
            lsum1 += (p10 + p11) + (p12 + p13);

            // single fp16-RN A fragment (unbiased rounding)
            uint32_t a0 = pack_half2(p00, p01), a2 = pack_half2(p02, p03);
            uint32_t a1 = pack_half2(p10, p11), a3 = pack_half2(p12, p13);

            // base byte offset within a B n-row for this chunk + lane k
            const int kOff = c * 32 + qm * 4;
#pragma unroll
            for (int nt = 0; nt < 8; ++nt) {
                const unsigned char* bp = Bs + (nt * 8 + qr) * BSTRIDE + kOff;
                uint32_t bh0 = *(const uint32_t*)bp;
                uint32_t bh1 = *(const uint32_t*)(bp + 16);
                uint32_t bl0 = *(const uint32_t*)(bp + BHALF);
                uint32_t bl1 = *(const uint32_t*)(bp + BHALF + 16);
                mma16816f16(d[nt], a0, a1, a2, a3, bh0, bh1);   // A * Whi
                mma16816f16(d[nt], a0, a1, a2, a3, bl0, bl1);   // A * Wlo
            }
        }
    }

    // ---- row sums: reduce across the 4 lanes of each quad-column group
    lsum0 += __shfl_xor_sync(0xffffffffu, lsum0, 1);
    lsum0 += __shfl_xor_sync(0xffffffffu, lsum0, 2);
    lsum1 += __shfl_xor_sync(0xffffffffu, lsum1, 1);
    lsum1 += __shfl_xor_sync(0xffffffffu, lsum1, 2);
    if (qm == 0) {
        g_lP[split][iBase + r0] = lsum0;
        g_lP[split][iBase + r1] = lsum1;
    }

    // ---- write partials: d[nt] = rows (r0, r1), cols nt*8 + 2*qm + {0,1}
    {
        float* base0 = &g_accP[split][iBase + r0][0];
        float* base1 = &g_accP[split][iBase + r1][0];
#pragma unroll
        for (int nt = 0; nt < 8; ++nt) {
            int cb = nt * 8 + 2 * qm;
            *(float2*)&base0[cb] = make_float2(d[nt][0], d[nt][1]);
            *(float2*)&base1[cb] = make_float2(d[nt][2], d[nt][3]);
        }
    }
}

// ---------------------------------------------------------------------------
// Kernel 3: sum split partials -> normalize -> ELU.
// ---------------------------------------------------------------------------
__global__ __launch_bounds__(256) void combine_kernel(float* __restrict__ out) {
    __shared__ float linv_s[16];
    const int t = threadIdx.x;
    const int rowBase = blockIdx.x * 16;

    if (t < 16) {
        int row = rowBase + t;
        float L = 0.f;
#pragma unroll
        for (int s = 0; s < SPLITS; ++s) L += g_lP[s][row];
        linv_s[t] = 1.f / L;
    }
    __syncthreads();

    const int rr = t >> 4;
    const int c4 = t & 15;
    const int row = rowBase + rr;

    float4 acc = make_float4(0.f, 0.f, 0.f, 0.f);
#pragma unroll
    for (int s = 0; s < SPLITS; ++s) {
        float4 v = *(const float4*)&g_accP[s][row][c4 * 4];
        acc.x += v.x; acc.y += v.y; acc.z += v.z; acc.w += v.w;
    }
    float li = linv_s[rr];
    float x0 = acc.x * li, x1 = acc.y * li, x2 = acc.z * li, x3 = acc.w * li;
    x0 = (x0 > 0.f) ? x0 : expm1f(x0);
    x1 = (x1 > 0.f) ? x1 : expm1f(x1);
    x2 = (x2 > 0.f) ? x2 : expm1f(x2);
    x3 = (x3 > 0.f) ? x3 : expm1f(x3);
    *(float4*)&out[(size_t)row * OUT_F + c4 * 4] = make_float4(x0, x1, x2, x3);
}

// ---------------------------------------------------------------------------
extern "C" void kernel_launch(void* const* d_in, const int* in_sizes, int n_in,
                              void* d_out, int out_size) {
    const float* h   = (const float*)d_in[0];   // 8192 x 128
    const int*   adj = (const int*)d_in[1];     // 8192 x 8192
    const float* W   = (const float*)d_in[2];   // 128 x 64
    const float* a   = (const float*)d_in[3];   // 128 x 1
    float* out = (float*)d_out;                 // 8192 x 64

    wh_kernel<<<NN / 16, 256>>>(h, W, a);
    attn_kernel<<<dim3(NTI, SPLITS), 256>>>(adj);
    combine_kernel<<<NN / 16, 256>>>(out);
}

// round 12
// speedup vs baseline: 1.6738x; 1.1836x over previous
#include <cuda_runtime.h>
#include <cuda_fp16.h>
#include <cstdint>

#define NN 8192
#define IN_F 128
#define OUT_F 64
#define ALPHA 0.2f

#define TI 128                 // CTA row tile
#define BK 128                 // j per B stage
#define SPLITS 8
#define JSPAN (NN / SPLITS)    // 1024
#define NTI (NN / TI)          // 64

#define BSTRIDE 272            // bytes per n-row in B stage (128*2 + 16 pad) -> conflict-free
#define BTOTAL  17408          // 64 * 272

// Scratch
__device__ float g_s1[NN];
__device__ float g_s2[NN];
__device__ __half g_WhT[OUT_F * NN];      // transposed Wh, fp16 (RN)
__device__ float g_accP[SPLITS][NN][OUT_F];
__device__ float g_lP[SPLITS][NN];

__device__ __forceinline__ uint32_t pack_half2(float x0, float x1) {
    __half2 h = __floats2half2_rn(x0, x1);
    return *(uint32_t*)&h;
}

__device__ __forceinline__ void mma16816f16(float* d,
                                            uint32_t a0, uint32_t a1, uint32_t a2, uint32_t a3,
                                            uint32_t b0, uint32_t b1) {
    asm volatile(
        "mma.sync.aligned.m16n8k16.row.col.f32.f16.f16.f32 "
        "{%0,%1,%2,%3}, {%4,%5,%6,%7}, {%8,%9}, {%0,%1,%2,%3};"
        : "+f"(d[0]), "+f"(d[1]), "+f"(d[2]), "+f"(d[3])
        : "r"(a0), "r"(a1), "r"(a2), "r"(a3), "r"(b0), "r"(b1));
}

// ---------------------------------------------------------------------------
// Kernel 1: Wh = h@W; s1 = Wh@a1; s2 = Wh@a2; WhT fp16 (RN).
// (round-6 structure, measured ~25us)
// ---------------------------------------------------------------------------
__global__ __launch_bounds__(256) void wh_kernel(const float* __restrict__ h,
                                                 const float* __restrict__ W,
                                                 const float* __restrict__ a) {
    __shared__ float W_s[IN_F * OUT_F];
    __shared__ float h_s[4][IN_F];
    __shared__ float a_s[2 * OUT_F];
    __shared__ float red1[8], red2[8];
    __shared__ float tr[OUT_F][17];

    const int t = threadIdx.x;
    const int blockRow = blockIdx.x * 16;

    for (int i = t; i < IN_F * OUT_F; i += 256) W_s[i] = W[i];
    if (t < 2 * OUT_F) a_s[t] = a[t];

    const int g = t >> 6;
    const int c = t & 63;

    for (int rg = 0; rg < 4; ++rg) {
        const int rowBase = blockRow + rg * 4;
        __syncthreads();
        for (int i = t; i < 4 * IN_F; i += 256)
            h_s[i >> 7][i & 127] = h[(size_t)(rowBase + (i >> 7)) * IN_F + (i & 127)];
        __syncthreads();

        float acc = 0.f;
#pragma unroll 8
        for (int k = 0; k < IN_F; ++k)
            acc += h_s[g][k] * W_s[k * OUT_F + c];

        tr[c][rg * 4 + g] = acc;

        float v1 = acc * a_s[c];
        float v2 = acc * a_s[OUT_F + c];
#pragma unroll
        for (int off = 16; off > 0; off >>= 1) {
            v1 += __shfl_down_sync(0xffffffffu, v1, off);
            v2 += __shfl_down_sync(0xffffffffu, v2, off);
        }
        if ((t & 31) == 0) { red1[t >> 5] = v1; red2[t >> 5] = v2; }
        __syncthreads();
        if (t < 4) {
            g_s1[rowBase + t] = red1[2 * t] + red1[2 * t + 1];
            g_s2[rowBase + t] = red2[2 * t] + red2[2 * t + 1];
        }
    }
    __syncthreads();

    // transposed fp16 write-out: thread t -> col cc=t>>2, rows q*4..+3
    {
        const int cc = t >> 2;
        const int q = t & 3;
        float v[4];
#pragma unroll
        for (int i = 0; i < 4; ++i) v[i] = tr[cc][q * 4 + i];
        size_t o = (size_t)cc * NN + blockRow + q * 4;
        *(uint2*)&g_WhT[o] = make_uint2(pack_half2(v[0], v[1]), pack_half2(v[2], v[3]));
    }
}

// ---------------------------------------------------------------------------
// Kernel 2: mma.sync fp16 attention — single MMA per n-tile (A and B both
// fp16-RN; unbiased rounding errors average down across neighbors).
// grid=(64 i-tiles, 8 splits), 8 warps.
// ---------------------------------------------------------------------------
__global__ void __launch_bounds__(256) attn_kernel(const int* __restrict__ adj) {
    __shared__ __align__(16) unsigned char Bs[BTOTAL];   // 64 rows x 272B
    __shared__ __align__(16) float s2_s[JSPAN];

    const int t = threadIdx.x;
    const int wid = t >> 5;
    const int lane = t & 31;
    const int qr = lane >> 2;      // 0..7
    const int qm = lane & 3;       // 0..3

    const int iBase = blockIdx.x * TI;
    const int split = blockIdx.y;
    const int jStart = split * JSPAN;

    const int r0 = wid * 16 + qr;      // local row for a0/a2
    const int r1 = r0 + 8;             // a1/a3
    const float s1r0 = g_s1[iBase + r0];
    const float s1r1 = g_s1[iBase + r1];
    const int* __restrict__ row0 = adj + (size_t)(iBase + r0) * NN;
    const int* __restrict__ row1 = adj + (size_t)(iBase + r1) * NN;

    // s2 span -> smem
    {
        const float4* src = (const float4*)&g_s2[jStart];
        ((float4*)s2_s)[t] = src[t];
    }

    float d[8][4];
#pragma unroll
    for (int nt = 0; nt < 8; ++nt)
#pragma unroll
        for (int i = 0; i < 4; ++i) d[nt][i] = 0.f;
    float lsum0 = 0.f, lsum1 = 0.f;

    for (int stage = 0; stage < JSPAN / BK; ++stage) {
        const int jStage = jStart + stage * BK;

        __syncthreads();   // prior MMAs done before overwriting Bs (also covers s2 on stage 0)

        // ---- load B stage: WhT fp16, 64 n-rows x 128 k, padded stride
        for (int idx = t; idx < 1024; idx += 256) {
            int n = idx >> 4;              // 0..63
            int seg = idx & 15;            // 16B segment
            const __half* gsrc = g_WhT + (size_t)n * NN + jStage;
            uint4 v = ((const uint4*)gsrc)[seg];
            *(uint4*)(Bs + n * BSTRIDE + seg * 16) = v;
        }
        __syncthreads();

        // ---- 8 chunks of 16 j
#pragma unroll 2
        for (int c = 0; c < 8; ++c) {
            const int jc = stage * BK + c * 16 + 2 * qm;   // local j (within span)
            const int gj = jStage + c * 16 + 2 * qm;       // global j

            int2 A0 = __ldg((const int2*)(row0 + gj));
            int2 A2 = __ldg((const int2*)(row0 + gj + 8));
            int2 A1 = __ldg((const int2*)(row1 + gj));
            int2 A3 = __ldg((const int2*)(row1 + gj + 8));
            float2 s2a = *(const float2*)&s2_s[jc];
            float2 s2b = *(const float2*)&s2_s[jc + 8];

            float e, p00, p01, p02, p03, p10, p11, p12, p13;
            e = s1r0 + s2a.x; e = fmaxf(e, ALPHA * e); p00 = (A0.x > 0) ? __expf(e) : 0.f;
            e = s1r0 + s2a.y; e = fmaxf(e, ALPHA * e); p01 = (A0.y > 0) ? __expf(e) : 0.f;
            e = s1r0 + s2b.x; e = fmaxf(e, ALPHA * e); p02 = (A2.x > 0) ? __expf(e) : 0.f;
            e = s1r0 + s2b.y; e = fmaxf(e, ALPHA * e); p03 = (A2.y > 0) ? __expf(e) : 0.f;
            e = s1r1 + s2a.x; e = fmaxf(e, ALPHA * e); p10 = (A1.x > 0) ? __expf(e) : 0.f;
            e = s1r1 + s2a.y; e = fmaxf(e, ALPHA * e); p11 = (A1.y > 0) ? __expf(e) : 0.f;
            e = s1r1 + s2b.x; e = fmaxf(e, ALPHA * e); p12 = (A3.x > 0) ? __expf(e) : 0.f;
            e = s1r1 + s2b.y; e = fmaxf(e, ALPHA * e); p13 = (A3.y > 0) ? __expf(e) : 0.f;

            lsum0 += (p00 + p01) + (p02 + p03);
            lsum1 += (p10 + p11) + (p12 + p13);

            // single fp16-RN A fragment
            uint32_t a0 = pack_half2(p00, p01), a2 = pack_half2(p02, p03);
            uint32_t a1 = pack_half2(p10, p11), a3 = pack_half2(p12, p13);

            const int kOff = c * 32 + qm * 4;
#pragma unroll
            for (int nt = 0; nt < 8; ++nt) {
                const unsigned char* bp = Bs + (nt * 8 + qr) * BSTRIDE + kOff;
                uint32_t b0 = *(const uint32_t*)bp;
                uint32_t b1 = *(const uint32_t*)(bp + 16);
                mma16816f16(d[nt], a0, a1, a2, a3, b0, b1);
            }
        }
    }

    // ---- row sums: reduce across the 4 lanes of each quad-column group
    lsum0 += __shfl_xor_sync(0xffffffffu, lsum0, 1);
    lsum0 += __shfl_xor_sync(0xffffffffu, lsum0, 2);
    lsum1 += __shfl_xor_sync(0xffffffffu, lsum1, 1);
    lsum1 += __shfl_xor_sync(0xffffffffu, lsum1, 2);
    if (qm == 0) {
        g_lP[split][iBase + r0] = lsum0;
        g_lP[split][iBase + r1] = lsum1;
    }

    // ---- write partials: d[nt] = rows (r0, r1), cols nt*8 + 2*qm + {0,1}
    {
        float* base0 = &g_accP[split][iBase + r0][0];
        float* base1 = &g_accP[split][iBase + r1][0];
#pragma unroll
        for (int nt = 0; nt < 8; ++nt) {
            int cb = nt * 8 + 2 * qm;
            *(float2*)&base0[cb] = make_float2(d[nt][0], d[nt][1]);
            *(float2*)&base1[cb] = make_float2(d[nt][2], d[nt][3]);
        }
    }
}

// ---------------------------------------------------------------------------
// Kernel 3: sum split partials -> normalize -> ELU.
// ---------------------------------------------------------------------------
__global__ __launch_bounds__(256) void combine_kernel(float* __restrict__ out) {
    __shared__ float linv_s[16];
    const int t = threadIdx.x;
    const int rowBase = blockIdx.x * 16;

    if (t < 16) {
        int row = rowBase + t;
        float L = 0.f;
#pragma unroll
        for (int s = 0; s < SPLITS; ++s) L += g_lP[s][row];
        linv_s[t] = 1.f / L;
    }
    __syncthreads();

    const int rr = t >> 4;
    const int c4 = t & 15;
    const int row = rowBase + rr;

    float4 acc = make_float4(0.f, 0.f, 0.f, 0.f);
#pragma unroll
    for (int s = 0; s < SPLITS; ++s) {
        float4 v = *(const float4*)&g_accP[s][row][c4 * 4];
        acc.x += v.x; acc.y += v.y; acc.z += v.z; acc.w += v.w;
    }
    float li = linv_s[rr];
    float x0 = acc.x * li, x1 = acc.y * li, x2 = acc.z * li, x3 = acc.w * li;
    x0 = (x0 > 0.f) ? x0 : expm1f(x0);
    x1 = (x1 > 0.f) ? x1 : expm1f(x1);
    x2 = (x2 > 0.f) ? x2 : expm1f(x2);
    x3 = (x3 > 0.f) ? x3 : expm1f(x3);
    *(float4*)&out[(size_t)row * OUT_F + c4 * 4] = make_float4(x0, x1, x2, x3);
}

// ---------------------------------------------------------------------------
extern "C" void kernel_launch(void* const* d_in, const int* in_sizes, int n_in,
                              void* d_out, int out_size) {
    const float* h   = (const float*)d_in[0];   // 8192 x 128
    const int*   adj = (const int*)d_in[1];     // 8192 x 8192
    const float* W   = (const float*)d_in[2];   // 128 x 64
    const float* a   = (const float*)d_in[3];   // 128 x 1
    float* out = (float*)d_out;                 // 8192 x 64

    wh_kernel<<<NN / 16, 256>>>(h, W, a);
    attn_kernel<<<dim3(NTI, SPLITS), 256>>>(adj);
    combine_kernel<<<NN / 16, 256>>>(out);
}